// round 1
// baseline (speedup 1.0000x reference)
#include <cuda_runtime.h>
#include <cuda_bf16.h>

#define BB 64
#define NQ 300
#define TT 30
#define BIGF 1e18f

// per-batch partial sums: [B][3] = {bce_sum, l1_sum, giou_sum}
__device__ float g_partials[BB * 3];

__global__ __launch_bounds__(256)
void detr_criterion_kernel(const float* __restrict__ pred_boxes,
                           const float* __restrict__ pred_classes,
                           const float* __restrict__ targets)
{
    __shared__ float cost[TT * NQ];     // [t][n]
    __shared__ float spc[NQ];
    __shared__ float v[NQ];
    __shared__ int   path[NQ];
    __shared__ int   row4col[NQ];
    __shared__ unsigned char SC[NQ];
    __shared__ unsigned char matched[NQ];
    __shared__ float u[TT];
    __shared__ unsigned char SR[TT];
    __shared__ int   col4row[TT];
    __shared__ int   sorted_idx[TT];
    __shared__ float warpsum[8];
    __shared__ float l1s[TT];
    __shared__ float gis[TT];

    const int b   = blockIdx.x;
    const int tid = threadIdx.x;
    const float* pb = pred_boxes  + (size_t)b * NQ * 4;
    const float* pc = pred_classes + (size_t)b * NQ;
    const float* tg = targets     + (size_t)b * TT * 4;

    // ---- cost matrix: cost[t][n] = -pc[n] - giou(pred n, tgt t) + L1(pred n, tgt t)
    for (int idx = tid; idx < TT * NQ; idx += blockDim.x) {
        int t = idx / NQ, n = idx % NQ;
        float px = pb[n * 4 + 0], py = pb[n * 4 + 1];
        float pw = pb[n * 4 + 2], ph = pb[n * 4 + 3];
        float tx = tg[t * 4 + 0], ty = tg[t * 4 + 1];
        float tw = tg[t * 4 + 2], th = tg[t * 4 + 3];

        float ax0 = px, ay0 = py, ax1 = px + pw, ay1 = py + ph;
        float bx0 = tx, by0 = ty, bx1 = tx + tw, by1 = ty + th;

        float area_a = (ax1 - ax0) * (ay1 - ay0);
        float area_b = (bx1 - bx0) * (by1 - by0);
        float iw = fmaxf(fminf(ax1, bx1) - fmaxf(ax0, bx0), 0.0f);
        float ih = fmaxf(fminf(ay1, by1) - fmaxf(ay0, by0), 0.0f);
        float inter = iw * ih;
        float uni = area_a + area_b - inter;
        float iou = inter / uni;
        float cw = fmaxf(fmaxf(ax1, bx1) - fminf(ax0, bx0), 0.0f);
        float ch = fmaxf(fmaxf(ay1, by1) - fminf(ay0, by0), 0.0f);
        float areac = cw * ch;
        float giou = iou - (areac - uni) / areac;

        float l1 = fabsf(px - tx) + fabsf(py - ty) + fabsf(pw - tw) + fabsf(ph - th);
        cost[idx] = -pc[n] - giou + l1;
    }
    for (int j = tid; j < NQ; j += blockDim.x) {
        v[j] = 0.0f; row4col[j] = -1; spc[j] = BIGF; SC[j] = 0; path[j] = 0; matched[j] = 0;
    }
    if (tid < TT) { u[tid] = 0.0f; SR[tid] = 0; col4row[tid] = -1; }
    __syncthreads();

    // ---- Hungarian (shortest augmenting path), warp 0 only, warp-synchronous
    if (tid < 32) {
        const int lane = tid;
        const unsigned FULL = 0xffffffffu;
        for (int row = 0; row < TT; ++row) {
            int cur_i = row;
            float minVal = 0.0f;
            int sink = -1;
            while (sink < 0) {
                if (lane == 0) SR[cur_i] = 1;
                float u_cur = u[cur_i];
                const float* crow = &cost[cur_i * NQ];
                float bestVal = BIGF;
                int bestJ = NQ;
                for (int j = lane; j < NQ; j += 32) {
                    if (!SC[j]) {
                        float red = minVal + crow[j] - u_cur - v[j];
                        float s = spc[j];
                        if (red < s) { s = red; spc[j] = red; path[j] = cur_i; }
                        if (s < bestVal) { bestVal = s; bestJ = j; } // ascending j: strict < keeps first
                    }
                }
                // warp argmin with first-index tie-break (matches jnp.argmin)
                #pragma unroll
                for (int off = 16; off; off >>= 1) {
                    float ov = __shfl_down_sync(FULL, bestVal, off);
                    int   oj = __shfl_down_sync(FULL, bestJ, off);
                    if (ov < bestVal || (ov == bestVal && oj < bestJ)) { bestVal = ov; bestJ = oj; }
                }
                bestVal = __shfl_sync(FULL, bestVal, 0);
                bestJ   = __shfl_sync(FULL, bestJ, 0);
                minVal = bestVal;
                if (lane == 0) SC[bestJ] = 1;
                int r = row4col[bestJ];   // only modified between rows (post-syncwarp)
                if (r < 0) sink = bestJ; else cur_i = r;
                __syncwarp();
            }
            // ---- dual updates (uses spc & col4row BEFORE augmentation)
            for (int j = lane; j < NQ; j += 32)
                if (SC[j]) v[j] -= (minVal - spc[j]);
            if (lane < TT) {
                if (lane == row) u[lane] += minVal;
                else if (SR[lane]) u[lane] += minVal - spc[col4row[lane]];
            }
            __syncwarp();
            // ---- augment along alternating path (serial, lane 0)
            if (lane == 0) {
                int j = sink;
                for (;;) {
                    int i = path[j];
                    row4col[j] = i;
                    int nj = col4row[i];
                    col4row[i] = j;
                    if (i == row) break;
                    j = nj;
                }
            }
            __syncwarp();
            // ---- reset for next row
            for (int j = lane; j < NQ; j += 32) { spc[j] = BIGF; SC[j] = 0; }
            if (lane < TT) SR[lane] = 0;
            __syncwarp();
        }
        // boxes_idx = sort(col4row); mark matched set
        if (lane == 0) {
            for (int i = 0; i < TT; ++i) sorted_idx[i] = col4row[i];
            for (int i = 1; i < TT; ++i) {
                int key = sorted_idx[i];
                int k = i - 1;
                while (k >= 0 && sorted_idx[k] > key) { sorted_idx[k + 1] = sorted_idx[k]; --k; }
                sorted_idx[k + 1] = key;
            }
            for (int i = 0; i < TT; ++i) matched[sorted_idx[i]] = 1;
        }
    }
    __syncthreads();

    // ---- BCE over all N queries
    float local = 0.0f;
    for (int n = tid; n < NQ; n += blockDim.x) {
        float p = pc[n];
        float lg = matched[n] ? logf(p) : logf(1.0f - p);
        local += -fmaxf(lg, -100.0f);
    }
    #pragma unroll
    for (int off = 16; off; off >>= 1)
        local += __shfl_down_sync(0xffffffffu, local, off);
    if ((tid & 31) == 0) warpsum[tid >> 5] = local;

    // ---- L1 + GIoU on matched (sorted-index) pairs
    if (tid < TT) {
        int t = tid;
        int n = sorted_idx[t];
        // NOTE: sorted_idx written by warp 0 before __syncthreads above... need it AFTER sync
        float px = pb[n * 4 + 0], py = pb[n * 4 + 1];
        float pw = pb[n * 4 + 2], ph = pb[n * 4 + 3];
        float tx = tg[t * 4 + 0], ty = tg[t * 4 + 1];
        float tw = tg[t * 4 + 2], th = tg[t * 4 + 3];
        l1s[t] = fabsf(px - tx) + fabsf(py - ty) + fabsf(pw - tw) + fabsf(ph - th);

        float ax0 = px, ay0 = py, ax1 = px + pw, ay1 = py + ph;
        float bx0 = tx, by0 = ty, bx1 = tx + tw, by1 = ty + th;
        float area_a = (ax1 - ax0) * (ay1 - ay0);
        float area_b = (bx1 - bx0) * (by1 - by0);
        float iw = fmaxf(fminf(ax1, bx1) - fmaxf(ax0, bx0), 0.0f);
        float ih = fmaxf(fminf(ay1, by1) - fmaxf(ay0, by0), 0.0f);
        float inter = iw * ih;
        float uni = area_a + area_b - inter;
        float iou = inter / uni;
        float cw = fmaxf(fmaxf(ax1, bx1) - fminf(ax0, bx0), 0.0f);
        float ch = fmaxf(fmaxf(ay1, by1) - fminf(ay0, by0), 0.0f);
        float areac = cw * ch;
        float giou = iou - (areac - uni) / areac;
        gis[t] = 1.0f - giou;
    }
    __syncthreads();

    if (tid == 0) {
        float bce = 0.0f;
        #pragma unroll
        for (int w = 0; w < 8; ++w) bce += warpsum[w];
        float l1 = 0.0f, gi = 0.0f;
        for (int t = 0; t < TT; ++t) { l1 += l1s[t]; gi += gis[t]; }
        g_partials[b * 3 + 0] = bce;
        g_partials[b * 3 + 1] = l1;
        g_partials[b * 3 + 2] = gi;
    }
}

__global__ void detr_reduce_kernel(float* __restrict__ out)
{
    int t = threadIdx.x;
    if (t < 3) {
        float s = 0.0f;
        for (int b = 0; b < BB; ++b) s += g_partials[b * 3 + t];
        float denom = (t == 0) ? (float)(BB * NQ) : (float)(BB * TT);
        out[t] = s / denom;
    }
}

extern "C" void kernel_launch(void* const* d_in, const int* in_sizes, int n_in,
                              void* d_out, int out_size)
{
    const float* pred_boxes = nullptr;
    const float* pred_classes = nullptr;
    const float* targets = nullptr;
    // identify by element count (robust to metadata order)
    for (int i = 0; i < n_in; ++i) {
        if (in_sizes[i] == BB * NQ * 4)      pred_boxes   = (const float*)d_in[i];
        else if (in_sizes[i] == BB * NQ)     pred_classes = (const float*)d_in[i];
        else if (in_sizes[i] == BB * TT * 4) targets      = (const float*)d_in[i];
    }
    float* out = (float*)d_out;
    detr_criterion_kernel<<<BB, 256>>>(pred_boxes, pred_classes, targets);
    detr_reduce_kernel<<<1, 32>>>(out);
}